// round 7
// baseline (speedup 1.0000x reference)
#include <cuda_runtime.h>

#define NN 8192

// ---- rank kernel geometry ----
#define RP 4                    // p-keys per thread (register blocked)
#define RANK_T 256              // threads per rank block
#define P_PER_BLK (RANK_T * RP) // 1024
#define PBLKS (NN / P_PER_BLK)  // 8
#define QSPLIT 32
#define QCHUNK (NN / QSPLIT)    // 256 (== one shared tile == RANK_T)

// ---- inversion kernel geometry ----
#define ITILE 1024
#define JTILE 256
#define INV_GX (NN / JTILE)     // 32
#define INV_GY (NN / ITILE)     // 8
#define INV_BLOCKS (INV_GX * INV_GY)  // 256

// Scratch (allocation-free)
__device__ unsigned int g_rpart[2][QSPLIT][NN];
__device__ int g_B[NN];
__device__ int g_tau[NN];
__device__ unsigned int g_count;
__device__ unsigned int g_done;

// Monotone uint32 mapping of float (total order == float < for finite values)
__device__ __forceinline__ unsigned int fkey(float f) {
    unsigned int u = __float_as_uint(f);
    return (u & 0x80000000u) ? ~u : (u | 0x80000000u);
}
__device__ __forceinline__ unsigned long long make_key(float f, int idx) {
    return (((unsigned long long)fkey(f)) << 13) | (unsigned int)idx; // idx<8192 fits 13 bits
}

// K1: partial ranks. grid=(PBLKS, QSPLIT, 2), block=RANK_T.
// Each thread owns RP p-keys, compares them against one shared tile of QCHUNK q-keys.
__global__ void rank_kernel(const float* __restrict__ X, const float* __restrict__ Xh) {
    __shared__ __align__(16) unsigned long long sh[QCHUNK];
    const int arr = blockIdx.z;
    const float* __restrict__ src = arr ? Xh : X;
    const int tid = threadIdx.x;

    const int q = blockIdx.y * QCHUNK + tid;
    sh[tid] = make_key(src[q], q);

    const int pbase = blockIdx.x * P_PER_BLK + tid;
    const unsigned long long k0 = make_key(src[pbase          ], pbase          );
    const unsigned long long k1 = make_key(src[pbase +     256], pbase +     256);
    const unsigned long long k2 = make_key(src[pbase + 2 * 256], pbase + 2 * 256);
    const unsigned long long k3 = make_key(src[pbase + 3 * 256], pbase + 3 * 256);
    __syncthreads();

    unsigned int c0 = 0, c1 = 0, c2 = 0, c3 = 0;
    const ulonglong2* __restrict__ sh2 = (const ulonglong2*)sh;
    #pragma unroll 8
    for (int j = 0; j < QCHUNK / 2; j++) {
        const ulonglong2 kq = sh2[j];
        c0 += (kq.x < k0); c1 += (kq.x < k1); c2 += (kq.x < k2); c3 += (kq.x < k3);
        c0 += (kq.y < k0); c1 += (kq.y < k1); c2 += (kq.y < k2); c3 += (kq.y < k3);
    }
    g_rpart[arr][blockIdx.y][pbase          ] = c0;
    g_rpart[arr][blockIdx.y][pbase +     256] = c1;
    g_rpart[arr][blockIdx.y][pbase + 2 * 256] = c2;
    g_rpart[arr][blockIdx.y][pbase + 3 * 256] = c3;
}

// K2: s[p] = full X_hat rank; scatter B[s[p]] = p  (B = argsort(X_hat))
__global__ void scatter_kernel() {
    const int p = blockIdx.x * 256 + threadIdx.x;
    unsigned int s = 0;
    #pragma unroll
    for (int z = 0; z < QSPLIT; z++) s += g_rpart[1][z][p];
    g_B[s] = p;
}

// K3: r[i] = full X rank; tau[i] = B[r[i]]; zero counters for the inversion pass.
__global__ void tau_kernel() {
    const int i = blockIdx.x * 256 + threadIdx.x;
    unsigned int r = 0;
    #pragma unroll
    for (int z = 0; z < QSPLIT; z++) r += g_rpart[0][z][i];
    g_tau[i] = g_B[r];
    if (i == 0) { g_count = 0; g_done = 0; }
}

// K4: inversions of tau over coarse triangular tiles (ITILE rows x JTILE cols),
// 4 rows per thread. Last finishing block writes the final answer.
__global__ void inv_kernel(float* __restrict__ out) {
    __shared__ __align__(16) int sh[JTILE];
    const int I = blockIdx.y, J = blockIdx.x;
    const int tid = threadIdx.x;
    const bool active = (J >= 4 * I);  // tile not entirely in lower triangle

    if (active) {
        sh[tid] = g_tau[J * JTILE + tid];
        const int i0 = I * ITILE + tid;
        const int v0 = g_tau[i0          ];
        const int v1 = g_tau[i0 +     256];
        const int v2 = g_tau[i0 + 2 * 256];
        const int v3 = g_tau[i0 + 3 * 256];
        __syncthreads();

        unsigned int cnt = 0;
        if (J >= 4 * I + 4) {
            // Full tile: every i < every j
            const int4* __restrict__ sh4 = (const int4*)sh;
            #pragma unroll 8
            for (int j = 0; j < JTILE / 4; j++) {
                const int4 s = sh4[j];
                cnt += (v0 > s.x) + (v0 > s.y) + (v0 > s.z) + (v0 > s.w);
                cnt += (v1 > s.x) + (v1 > s.y) + (v1 > s.z) + (v1 > s.w);
                cnt += (v2 > s.x) + (v2 > s.y) + (v2 > s.z) + (v2 > s.w);
                cnt += (v3 > s.x) + (v3 > s.y) + (v3 > s.z) + (v3 > s.w);
            }
        } else {
            // Diagonal band: mask i < j explicitly (only 32 such blocks)
            const int jg0 = J * JTILE;
            for (int j = 0; j < JTILE; j++) {
                const int jg = jg0 + j;
                const int s = sh[j];
                cnt += (i0           < jg) & (v0 > s);
                cnt += (i0 +     256 < jg) & (v1 > s);
                cnt += (i0 + 2 * 256 < jg) & (v2 > s);
                cnt += (i0 + 3 * 256 < jg) & (v3 > s);
            }
        }
        cnt = __reduce_add_sync(0xffffffffu, cnt);
        if ((tid & 31) == 0) atomicAdd(&g_count, cnt);
        __syncthreads();
    }

    // Completion detection: every block (active or not) signals; last one finalizes.
    if (tid == 0) {
        __threadfence();
        const unsigned int d = atomicAdd(&g_done, 1u);
        if (d == INV_BLOCKS - 1) {
            const unsigned int tot = atomicAdd(&g_count, 0u);  // coherent L2 read
            out[0] = (float)(2.0 * (double)tot / ((double)NN * (double)(NN - 1)));
        }
    }
}

extern "C" void kernel_launch(void* const* d_in, const int* in_sizes, int n_in,
                              void* d_out, int out_size) {
    const float* X  = (const float*)d_in[0];
    const float* Xh = (const float*)d_in[1];
    float* out = (float*)d_out;

    dim3 g1(PBLKS, QSPLIT, 2);
    rank_kernel<<<g1, RANK_T>>>(X, Xh);
    scatter_kernel<<<NN / 256, 256>>>();
    tau_kernel<<<NN / 256, 256>>>();
    dim3 g4(INV_GX, INV_GY);
    inv_kernel<<<g4, JTILE>>>(out);
}